// round 3
// baseline (speedup 1.0000x reference)
#include <cuda_runtime.h>
#include <cuda_fp16.h>
#include <cstdint>

// ----------------------------------------------------------------------------
// WQLinearGEMM: out[M,N] = x[M,K] @ dequant(qweight,qzeros,scales)[K,N] + bias
// AWQ int4 packing, GROUP_SIZE=128, unpack order [0,4,1,5,2,6,3,7].
// Round 3: harness promotes fp16 tensors to FLOAT32. x/scales/bias/out are
// float*. Dequant to fp16 scratch + mma.sync HGEMM; epilogue mimics the
// reference's fp16 rounding (round acc to f16, f16 bias add, widen to f32).
// ----------------------------------------------------------------------------

#define BM 128
#define BN 128
#define BK 64
#define APAD 8
#define BPAD 8

// 96 MB static device scratch for dequantized W (K=4096, N=12288 exact fit)
static __device__ __half g_wdeq[4096UL * 12288UL];

// ---------------------------- dequant kernel --------------------------------
__global__ void dequant_kernel(const int* __restrict__ qw,
                               const int* __restrict__ qz,
                               const float* __restrict__ scales,
                               int K, int N) {
    const int N8 = N >> 3;
    int idx = blockIdx.x * blockDim.x + threadIdx.x;
    int total = K * N8;
    if (idx >= total) return;
    int k  = idx / N8;
    int n8 = idx - k * N8;
    int g  = k >> 7;  // GROUP_SIZE = 128

    unsigned u = (unsigned)qw[idx];
    unsigned z = (unsigned)qz[g * N8 + n8];
    float4 s0 = *reinterpret_cast<const float4*>(scales + (size_t)g * N + n8 * 8);
    float4 s1 = *reinterpret_cast<const float4*>(scales + (size_t)g * N + n8 * 8 + 4);
    float s[8] = {s0.x, s0.y, s0.z, s0.w, s1.x, s1.y, s1.z, s1.w};

    // output element j comes from nibble {0,4,1,5,2,6,3,7}[j]
    __half outv[8];
#pragma unroll
    for (int j = 0; j < 8; ++j) {
        const int sh = (j & 1) ? (16 + (j >> 1) * 4) : ((j >> 1) * 4);
        int wq = (u >> sh) & 15;
        int zq = (z >> sh) & 15;
        // f32 product of (small exact int) * (exact f16 value) is exact;
        // RN to f16 == fp16 multiply of the reference.
        outv[j] = __float2half_rn((float)(wq - zq) * s[j]);
    }
    *reinterpret_cast<uint4*>(g_wdeq + (size_t)k * N + n8 * 8) =
        *reinterpret_cast<const uint4*>(outv);
}

// ------------------------------ GEMM helpers --------------------------------
__device__ __forceinline__ uint32_t smem_u32(const void* p) {
    return (uint32_t)__cvta_generic_to_shared(p);
}
__device__ __forceinline__ void cp_async16(uint32_t dst, const void* src) {
    asm volatile("cp.async.cg.shared.global [%0], [%1], 16;\n" :: "r"(dst), "l"(src));
}
__device__ __forceinline__ void cp_commit() {
    asm volatile("cp.async.commit_group;\n");
}
template <int NREM>
__device__ __forceinline__ void cp_wait() {
    asm volatile("cp.async.wait_group %0;\n" :: "n"(NREM));
}

// ------------------------------- GEMM kernel --------------------------------
// 256 threads, 8 warps arranged 2(M) x 4(N); warp tile 64x32 via m16n8k16.
// A: float32 in gmem, converted to fp16 on the way into SMEM.
// B: fp16 from dequant scratch via cp.async.
__global__ void gemm_kernel(const float* __restrict__ A,
                            const float* __restrict__ bias,
                            float* __restrict__ C,
                            int M, int N, int K) {
    extern __shared__ __half smem[];
    __half* As = smem;                               // [2][BM][BK+APAD]
    __half* Bs = smem + 2 * BM * (BK + APAD);        // [2][BK][BN+BPAD]
    const __half* B = g_wdeq;

    const int tid  = threadIdx.x;
    const int lane = tid & 31;
    const int warp = tid >> 5;
    const int wm = warp >> 2;  // 0..1
    const int wn = warp & 3;   // 0..3

    const int bm = blockIdx.y * BM;
    const int bn = blockIdx.x * BN;

    const int ASTRIDE = BK + APAD;
    const int BSTRIDE = BN + BPAD;

    float acc[4][4][4];
#pragma unroll
    for (int i = 0; i < 4; ++i)
#pragma unroll
        for (int j = 0; j < 4; ++j)
#pragma unroll
            for (int r = 0; r < 4; ++r) acc[i][j][r] = 0.0f;

    // A tile: BM*BK = 8192 floats, 256 threads -> 8 float4 per thread.
    auto prefetchA = [&](float4* regs, int kt) {
        const float* Ag = A + (size_t)bm * K + kt * BK;
#pragma unroll
        for (int it = 0; it < 8; ++it) {
            int f   = it * 256 + tid;
            int row = f >> 4;
            int c4  = (f & 15) * 4;
            regs[it] = *reinterpret_cast<const float4*>(Ag + (size_t)row * K + c4);
        }
    };
    auto storeA = [&](const float4* regs, int buf) {
#pragma unroll
        for (int it = 0; it < 8; ++it) {
            int f   = it * 256 + tid;
            int row = f >> 4;
            int c4  = (f & 15) * 4;
            __half2 h0 = __floats2half2_rn(regs[it].x, regs[it].y);
            __half2 h1 = __floats2half2_rn(regs[it].z, regs[it].w);
            uint2 u;
            u.x = *reinterpret_cast<const uint32_t*>(&h0);
            u.y = *reinterpret_cast<const uint32_t*>(&h1);
            *reinterpret_cast<uint2*>(As + buf * BM * ASTRIDE + row * ASTRIDE + c4) = u;
        }
    };
    // B tile: 64 rows x 16 uint4 (128 halves) = 1024 cp.async, 4 per thread
    auto loadB = [&](int buf, int kt) {
        const int k0 = kt * BK;
#pragma unroll
        for (int it = 0; it < 4; ++it) {
            int id  = it * 256 + tid;
            int row = id >> 4;
            int c4  = id & 15;
            uint32_t dst = smem_u32(Bs + buf * BK * BSTRIDE + row * BSTRIDE + c4 * 8);
            cp_async16(dst, B + (size_t)(k0 + row) * N + bn + c4 * 8);
        }
    };

    auto compute = [&](int buf) {
        uint32_t a[4][4];
        uint32_t b[4][2];
#pragma unroll
        for (int ks = 0; ks < BK / 16; ++ks) {
#pragma unroll
            for (int i = 0; i < 4; ++i) {
                int row = wm * 64 + i * 16 + (lane & 15);
                int col = ks * 16 + (lane >> 4) * 8;
                uint32_t addr = smem_u32(As + buf * BM * ASTRIDE + row * ASTRIDE + col);
                asm volatile(
                    "ldmatrix.sync.aligned.m8n8.x4.shared.b16 {%0,%1,%2,%3}, [%4];"
                    : "=r"(a[i][0]), "=r"(a[i][1]), "=r"(a[i][2]), "=r"(a[i][3])
                    : "r"(addr));
            }
#pragma unroll
            for (int j = 0; j < 4; ++j) {
                int row = ks * 16 + (lane & 15);
                int col = wn * 32 + j * 8;
                uint32_t addr = smem_u32(Bs + buf * BK * BSTRIDE + row * BSTRIDE + col);
                asm volatile(
                    "ldmatrix.sync.aligned.m8n8.x2.trans.shared.b16 {%0,%1}, [%2];"
                    : "=r"(b[j][0]), "=r"(b[j][1])
                    : "r"(addr));
            }
#pragma unroll
            for (int i = 0; i < 4; ++i)
#pragma unroll
                for (int j = 0; j < 4; ++j) {
                    asm volatile(
                        "mma.sync.aligned.m16n8k16.row.col.f32.f16.f16.f32 "
                        "{%0,%1,%2,%3}, {%4,%5,%6,%7}, {%8,%9}, {%0,%1,%2,%3};"
                        : "+f"(acc[i][j][0]), "+f"(acc[i][j][1]),
                          "+f"(acc[i][j][2]), "+f"(acc[i][j][3])
                        : "r"(a[i][0]), "r"(a[i][1]), "r"(a[i][2]), "r"(a[i][3]),
                          "r"(b[j][0]), "r"(b[j][1]));
                }
        }
    };

    const int KT = K / BK;
    // prologue: stage tile 0
    {
        float4 a0[8];
        prefetchA(a0, 0);
        storeA(a0, 0);
        loadB(0, 0);
        cp_commit();
    }
    float4 apre[8];
#pragma unroll 1
    for (int kt = 0; kt < KT; ++kt) {
        const int buf = kt & 1;
        if (kt + 1 < KT) {
            prefetchA(apre, kt + 1);   // overlap LDG latency with compute
            loadB(buf ^ 1, kt + 1);
            cp_commit();
            cp_wait<1>();
        } else {
            cp_wait<0>();
        }
        __syncthreads();
        compute(buf);
        __syncthreads();
        if (kt + 1 < KT) storeA(apre, buf ^ 1);
    }

    // epilogue: mimic reference fp16 path: round acc to f16, add f16 bias,
    // widen to f32 for the store.
#pragma unroll
    for (int i = 0; i < 4; ++i) {
#pragma unroll
        for (int j = 0; j < 4; ++j) {
            int m0 = bm + wm * 64 + i * 16 + (lane >> 2);
            int n0 = bn + wn * 32 + j * 8 + (lane & 3) * 2;
            __half hb0 = __float2half_rn(bias[n0]);
            __half hb1 = __float2half_rn(bias[n0 + 1]);
            float2 v01, v23;
            v01.x = __half2float(__hadd(__float2half_rn(acc[i][j][0]), hb0));
            v01.y = __half2float(__hadd(__float2half_rn(acc[i][j][1]), hb1));
            v23.x = __half2float(__hadd(__float2half_rn(acc[i][j][2]), hb0));
            v23.y = __half2float(__hadd(__float2half_rn(acc[i][j][3]), hb1));
            *reinterpret_cast<float2*>(C + (size_t)m0 * N + n0) = v01;
            *reinterpret_cast<float2*>(C + (size_t)(m0 + 8) * N + n0) = v23;
        }
    }
}

// ------------------------------- launch --------------------------------------
// Identify inputs by element count (robust to metadata ordering):
// |bias|=N < |qzeros|=G*N/8 < |scales|=G*N < |qweight|=K*N/8 < |x|=M*K.
extern "C" void kernel_launch(void* const* d_in, const int* in_sizes, int n_in,
                              void* d_out, int out_size) {
    int order[5] = {0, 1, 2, 3, 4};
    for (int i = 0; i < 5; ++i)
        for (int j = i + 1; j < 5; ++j)
            if ((long long)in_sizes[order[j]] < (long long)in_sizes[order[i]]) {
                int t = order[i]; order[i] = order[j]; order[j] = t;
            }
    const float* bias   = (const float*)d_in[order[0]];  // N
    const int*   qz     = (const int*)  d_in[order[1]];   // G*N/8
    const float* scales = (const float*)d_in[order[2]];   // G*N
    const int*   qw     = (const int*)  d_in[order[3]];   // K*N/8
    const float* x      = (const float*)d_in[order[4]];   // M*K
    float*       out    = (float*)d_out;

    const int N = in_sizes[order[0]];                                  // 12288
    const int K = (int)(((long long)in_sizes[order[3]] * 8) / N);      // 4096
    const int M = (int)((long long)in_sizes[order[4]] / K);            // 8192

    // 1) dequantize int4 -> fp16 scratch
    {
        int total   = K * (N >> 3);
        int threads = 256;
        int blocks  = (total + threads - 1) / threads;
        dequant_kernel<<<blocks, threads>>>(qw, qz, scales, K, N);
    }

    // 2) HGEMM with bias
    {
        const int smem_bytes =
            (2 * BM * (BK + APAD) + 2 * BK * (BN + BPAD)) * (int)sizeof(__half);
        cudaFuncSetAttribute(gemm_kernel,
                             cudaFuncAttributeMaxDynamicSharedMemorySize, smem_bytes);
        dim3 grid(N / BN, M / BM);
        gemm_kernel<<<grid, 256, smem_bytes>>>(x, bias, out, M, N, K);
    }
}

// round 5
// speedup vs baseline: 1.0923x; 1.0923x over previous
#include <cuda_runtime.h>
#include <cuda_fp16.h>
#include <cstdint>

// ----------------------------------------------------------------------------
// WQLinearGEMM: out[M,N] = x[M,K] @ dequant(qweight,qzeros,scales)[K,N] + bias
// Round 5: sm_103 (no 'a' target => no tcgen05). Max out mma.sync path:
//  - pre-pass: x f32->f16 scratch; dequant int4 -> fp16 W [K,N] scratch
//  - GEMM: CTA 128x256x32, 8 warps (warp tile 64x64), 4-stage cp.async
//    pipeline, one __syncthreads per iter, conflict-free ldmatrix layouts.
// ----------------------------------------------------------------------------

#define BM 128
#define BN 256
#define BK 32
#define STG 4
#define AST 40    // A smem row stride (halves): conflict-free ldmatrix
#define BST 264   // B smem row stride (halves): conflict-free ldmatrix.trans

// static scratch: x fp16 (64MB), W fp16 (96MB)
static __device__ __half g_xh[8192UL * 4096UL];
static __device__ __half g_wdeq[4096UL * 12288UL];

// ------------------------------ helpers -------------------------------------
__device__ __forceinline__ uint32_t smem_u32(const void* p) {
    return (uint32_t)__cvta_generic_to_shared(p);
}
__device__ __forceinline__ void cpa16(uint32_t dst, const void* src) {
    asm volatile("cp.async.cg.shared.global [%0], [%1], 16;\n" :: "r"(dst), "l"(src));
}
__device__ __forceinline__ void cp_commit() {
    asm volatile("cp.async.commit_group;\n");
}
template <int NREM>
__device__ __forceinline__ void cp_wait() {
    asm volatile("cp.async.wait_group %0;\n" :: "n"(NREM));
}

// ------------------------- pre-pass 1: x f32 -> f16 --------------------------
__global__ void cvt_x(const float* __restrict__ x, long long n4) {
    long long i = (long long)blockIdx.x * blockDim.x + threadIdx.x;
    if (i >= n4) return;
    float4 v = reinterpret_cast<const float4*>(x)[i];
    __half2 a = __floats2half2_rn(v.x, v.y);
    __half2 b = __floats2half2_rn(v.z, v.w);
    uint2 u;
    u.x = *reinterpret_cast<const uint32_t*>(&a);
    u.y = *reinterpret_cast<const uint32_t*>(&b);
    reinterpret_cast<uint2*>(g_xh)[i] = u;
}

// -------------------- pre-pass 2: dequant int4 -> fp16 [K,N] -----------------
__global__ void dequant_kernel(const int* __restrict__ qw,
                               const int* __restrict__ qz,
                               const float* __restrict__ scales,
                               int K, int N) {
    const int N8 = N >> 3;
    int idx = blockIdx.x * blockDim.x + threadIdx.x;
    int total = K * N8;
    if (idx >= total) return;
    int k  = idx / N8;
    int n8 = idx - k * N8;
    int g  = k >> 7;  // GROUP_SIZE = 128

    unsigned u = (unsigned)qw[idx];
    unsigned z = (unsigned)qz[g * N8 + n8];
    float4 s0 = *reinterpret_cast<const float4*>(scales + (size_t)g * N + n8 * 8);
    float4 s1 = *reinterpret_cast<const float4*>(scales + (size_t)g * N + n8 * 8 + 4);
    float s[8] = {s0.x, s0.y, s0.z, s0.w, s1.x, s1.y, s1.z, s1.w};

    __half outv[8];
#pragma unroll
    for (int j = 0; j < 8; ++j) {
        // output element j comes from nibble {0,4,1,5,2,6,3,7}[j]
        const int sh = (j & 1) ? (16 + (j >> 1) * 4) : ((j >> 1) * 4);
        int wq = (u >> sh) & 15;
        int zq = (z >> sh) & 15;
        outv[j] = __float2half_rn((float)(wq - zq) * s[j]);
    }
    *reinterpret_cast<uint4*>(g_wdeq + (size_t)k * N + n8 * 8) =
        *reinterpret_cast<const uint4*>(outv);
}

// ------------------------------- GEMM kernel --------------------------------
__global__ __launch_bounds__(256, 1)
void gemm_hmma(const float* __restrict__ bias, float* __restrict__ C,
               int M, int N, int K) {
    extern __shared__ __half sm[];
    __half* As = sm;                       // [STG][BM][AST]
    __half* Bs = sm + STG * BM * AST;      // [STG][BK][BST]

    const int tid  = threadIdx.x;
    const int lane = tid & 31;
    const int warp = tid >> 5;
    const int wm = warp >> 2;  // 0..1
    const int wn = warp & 3;   // 0..3

    const int bm = blockIdx.y * BM;
    const int bn = blockIdx.x * BN;
    const int KT = K / BK;

    const __half* Ag = g_xh   + (size_t)bm * K;
    const __half* Bg = g_wdeq + (size_t)bn;

    float acc[4][8][4];
#pragma unroll
    for (int i = 0; i < 4; ++i)
#pragma unroll
        for (int j = 0; j < 8; ++j)
#pragma unroll
            for (int r = 0; r < 4; ++r) acc[i][j][r] = 0.0f;

    // per-thread load coords (hoisted)
    const int ar = tid >> 2;            // A row (0..63), +64 for it=1
    const int ac = (tid & 3) * 8;       // A col
    const int br = tid >> 5;            // B row (0..7), +8/16/24
    const int bc = (tid & 31) * 8;      // B col

    auto load_stage = [&](int s, int kt) {
        const __half* Asrc = Ag + kt * BK;
        uint32_t ad = smem_u32(As + s * BM * AST);
#pragma unroll
        for (int it = 0; it < 2; ++it) {
            int r = ar + it * 64;
            cpa16(ad + (r * AST + ac) * 2, Asrc + (size_t)r * K + ac);
        }
        const __half* Bsrc = Bg + (size_t)(kt * BK) * N;
        uint32_t bd = smem_u32(Bs + s * BK * BST);
#pragma unroll
        for (int it = 0; it < 4; ++it) {
            int r = br + it * 8;
            cpa16(bd + (r * BST + bc) * 2, Bsrc + (size_t)r * N + bc);
        }
    };

    // prologue: stages 0..STG-2
#pragma unroll
    for (int p = 0; p < STG - 1; ++p) {
        load_stage(p, p);
        cp_commit();
    }

#pragma unroll 1
    for (int kt = 0; kt < KT; ++kt) {
        cp_wait<STG - 2>();
        __syncthreads();
        // issue next stage (writes a stage all warps finished last iter)
        int nk = kt + STG - 1;
        if (nk < KT) load_stage(nk % STG, nk);
        cp_commit();

        // compute on stage kt%STG
        const int s = kt % STG;
        uint32_t abase = smem_u32(As + s * BM * AST);
        uint32_t bbase = smem_u32(Bs + s * BK * BST);
#pragma unroll
        for (int ks = 0; ks < BK / 16; ++ks) {
            uint32_t a[4][4];
            uint32_t b[8][2];
#pragma unroll
            for (int i = 0; i < 4; ++i) {
                int row = wm * 64 + i * 16 + (lane & 15);
                int col = ks * 16 + (lane >> 4) * 8;
                asm volatile(
                    "ldmatrix.sync.aligned.m8n8.x4.shared.b16 {%0,%1,%2,%3}, [%4];"
                    : "=r"(a[i][0]), "=r"(a[i][1]), "=r"(a[i][2]), "=r"(a[i][3])
                    : "r"(abase + (row * AST + col) * 2));
            }
#pragma unroll
            for (int j = 0; j < 8; ++j) {
                int row = ks * 16 + (lane & 15);
                int col = wn * 64 + j * 8;
                asm volatile(
                    "ldmatrix.sync.aligned.m8n8.x2.trans.shared.b16 {%0,%1}, [%2];"
                    : "=r"(b[j][0]), "=r"(b[j][1])
                    : "r"(bbase + (row * BST + col) * 2));
            }
#pragma unroll
            for (int i = 0; i < 4; ++i)
#pragma unroll
                for (int j = 0; j < 8; ++j) {
                    asm volatile(
                        "mma.sync.aligned.m16n8k16.row.col.f32.f16.f16.f32 "
                        "{%0,%1,%2,%3}, {%4,%5,%6,%7}, {%8,%9}, {%0,%1,%2,%3};"
                        : "+f"(acc[i][j][0]), "+f"(acc[i][j][1]),
                          "+f"(acc[i][j][2]), "+f"(acc[i][j][3])
                        : "r"(a[i][0]), "r"(a[i][1]), "r"(a[i][2]), "r"(a[i][3]),
                          "r"(b[j][0]), "r"(b[j][1]));
                }
        }
    }

    // epilogue: round acc to f16, add f16 bias, widen to f32 (matches reference)
#pragma unroll
    for (int j = 0; j < 8; ++j) {
        int n0 = bn + wn * 64 + j * 8 + (lane & 3) * 2;
        __half hb0 = __float2half_rn(__ldg(bias + n0));
        __half hb1 = __float2half_rn(__ldg(bias + n0 + 1));
#pragma unroll
        for (int i = 0; i < 4; ++i) {
            int m0 = bm + wm * 64 + i * 16 + (lane >> 2);
            float2 v01, v23;
            v01.x = __half2float(__hadd(__float2half_rn(acc[i][j][0]), hb0));
            v01.y = __half2float(__hadd(__float2half_rn(acc[i][j][1]), hb1));
            v23.x = __half2float(__hadd(__float2half_rn(acc[i][j][2]), hb0));
            v23.y = __half2float(__hadd(__float2half_rn(acc[i][j][3]), hb1));
            *reinterpret_cast<float2*>(C + (size_t)m0 * N + n0) = v01;
            *reinterpret_cast<float2*>(C + (size_t)(m0 + 8) * N + n0) = v23;
        }
    }
}

// ------------------------------- launch --------------------------------------
// Identify inputs by element count (robust to metadata ordering):
// |bias|=N < |qzeros|=G*N/8 < |scales|=G*N < |qweight|=K*N/8 < |x|=M*K.
extern "C" void kernel_launch(void* const* d_in, const int* in_sizes, int n_in,
                              void* d_out, int out_size) {
    int order[5] = {0, 1, 2, 3, 4};
    for (int i = 0; i < 5; ++i)
        for (int j = i + 1; j < 5; ++j)
            if ((long long)in_sizes[order[j]] < (long long)in_sizes[order[i]]) {
                int t = order[i]; order[i] = order[j]; order[j] = t;
            }
    const float* bias   = (const float*)d_in[order[0]];   // N
    const int*   qz     = (const int*)  d_in[order[1]];    // G*N/8
    const float* scales = (const float*)d_in[order[2]];    // G*N
    const int*   qw     = (const int*)  d_in[order[3]];    // K*N/8
    const float* x      = (const float*)d_in[order[4]];    // M*K
    float*       out    = (float*)d_out;

    const int N = in_sizes[order[0]];                              // 12288
    const int K = (int)(((long long)in_sizes[order[3]] * 8) / N);  // 4096
    const int M = (int)((long long)in_sizes[order[4]] / K);        // 8192

    // 1) x f32 -> f16
    {
        long long n4 = (long long)M * K / 4;
        int threads = 256;
        long long blocks = (n4 + threads - 1) / threads;
        cvt_x<<<(unsigned)blocks, threads>>>(x, n4);
    }
    // 2) dequant int4 -> fp16 [K,N]
    {
        int total   = K * (N >> 3);
        int threads = 256;
        int blocks  = (total + threads - 1) / threads;
        dequant_kernel<<<blocks, threads>>>(qw, qz, scales, K, N);
    }
    // 3) GEMM
    {
        const int smem_bytes = (STG * BM * AST + STG * BK * BST) * (int)sizeof(__half);
        cudaFuncSetAttribute(gemm_hmma,
                             cudaFuncAttributeMaxDynamicSharedMemorySize, smem_bytes);
        dim3 grid(N / BN, M / BM);
        gemm_hmma<<<grid, 256, smem_bytes>>>(bias, out, M, N, K);
    }
}